// round 9
// baseline (speedup 1.0000x reference)
#include <cuda_runtime.h>

// out[b, q, j] = float( max(0, q - 127) + j )   for B=8, Q=4096, K=64.
//
// Derivation: reference masks local window [q-127, q] to +inf, future
// (k>q) to -inf, then stable top_k(64) (lowest index wins ties) -> always
// the 64 lowest window indices = max(0,q-127)+0..63. Input I is
// irrelevant; output buffer dtype is float32 (confirmed R1/R2).
//
// R8 post-mortem: 2048->512 CTAs at constant threads gained 6% -> the
// CTA-scheduling ramp is a real component of the latency floor. Continue
// the gradient: 256 CTAs x 1024 threads, 2 float4 per thread. Still one
// wave (1.7 CTA/SM, up to 64 warps/SM), instruction count halved.

__global__ void __launch_bounds__(1024)
TokenSelector_17755394801797_kernel(float4* __restrict__ out) {
    int idx = blockIdx.x * 1024 + threadIdx.x;  // 0..262143, two float4 each
    // First float4 of this thread's pair: element index = idx*8
    int lin = idx << 3;
    int j   = lin & 63;                         // within-row position (mult of 8)
    int q   = (lin >> 6) & 4095;                // query row
    int start = max(q - 127, 0);
    float base = (float)(start + j);

    float4 v0, v1;
    v0.x = base;        v0.y = base + 1.0f;
    v0.z = base + 2.0f; v0.w = base + 3.0f;
    v1.x = base + 4.0f; v1.y = base + 5.0f;
    v1.z = base + 6.0f; v1.w = base + 7.0f;

    float4* p = out + (idx << 1);
    p[0] = v0;
    p[1] = v1;
}

extern "C" void kernel_launch(void* const* d_in, const int* in_sizes, int n_in,
                              void* d_out, int out_size) {
    (void)d_in; (void)in_sizes; (void)n_in; (void)out_size;
    // 2,097,152 floats / 8 per thread / 1024 threads = 256 blocks, exact.
    TokenSelector_17755394801797_kernel<<<256, 1024>>>((float4*)d_out);
}